// round 15
// baseline (speedup 1.0000x reference)
#include <cuda_runtime.h>

#define NPTS (96*96*96)   // 884736
#define HID 64
#define TPB 128
#define PPT 6             // points per thread = 3 packed pairs
#define NQ  3
#define NNEWT 48          // h in [0,NNEWT): FMA-Newton reciprocal; rest: MUFU rcp

typedef unsigned long long u64;

// Per-h weight record (4 x ulonglong2 = 64B):
//  A={w0d,w1d} B={w2d,bbd}  (W1 rows & b1, prescaled by 2*log2e, duplicated)
//  C={v0d,v1d} D={v2d,pad}  (h<NNEWT: +2*W2 dup; h>=NNEWT: -2*W2 dup)
__constant__ ulonglong2 c_w[2][HID][4];
__constant__ float      c_S[2][4];       // S_j = b2_j + sum_h W2[h][j]

__device__ ulonglong2 g_scratch_w[2][HID][4];
__device__ float      g_scratch_S[2][4];

__device__ __forceinline__ u64 pk2(float lo, float hi) {
    u64 r; asm("mov.b64 %0,{%1,%2};" : "=l"(r) : "f"(lo), "f"(hi)); return r;
}
__device__ __forceinline__ void upk2(u64 v, float& lo, float& hi) {
    asm("mov.b64 {%0,%1},%2;" : "=f"(lo), "=f"(hi) : "l"(v));
}
__device__ __forceinline__ u64 fma2(u64 a, u64 b, u64 c) {
    u64 d; asm("fma.rn.f32x2 %0,%1,%2,%3;" : "=l"(d) : "l"(a), "l"(b), "l"(c)); return d;
}
__device__ __forceinline__ u64 mul2(u64 a, u64 b) {
    u64 d; asm("mul.rn.f32x2 %0,%1,%2;" : "=l"(d) : "l"(a), "l"(b)); return d;
}
__device__ __forceinline__ u64 add2(u64 a, u64 b) {
    u64 d; asm("add.rn.f32x2 %0,%1,%2;" : "=l"(d) : "l"(a), "l"(b)); return d;
}
// e2 = 2^(u2) per packed lane
__device__ __forceinline__ u64 ex2pair(u64 u2) {
    u64 e2;
    asm("{\n\t"
        ".reg .f32 a, b;\n\t"
        "mov.b64 {a, b}, %1;\n\t"
        "ex2.approx.f32 a, a;\n\t"
        "ex2.approx.f32 b, b;\n\t"
        "mov.b64 %0, {a, b};\n\t"
        "}" : "=l"(e2) : "l"(u2));
    return e2;
}
// r2 = 1/(1+2^u) per packed lane
__device__ __forceinline__ u64 sigpair(u64 u2) {
    u64 r2;
    asm("{\n\t"
        ".reg .f32 a, b;\n\t"
        "mov.b64 {a, b}, %1;\n\t"
        "ex2.approx.f32 a, a;\n\t"
        "ex2.approx.f32 b, b;\n\t"
        "add.f32 a, a, 0f3F800000;\n\t"
        "add.f32 b, b, 0f3F800000;\n\t"
        "rcp.approx.f32 a, a;\n\t"
        "rcp.approx.f32 b, b;\n\t"
        "mov.b64 %0, {a, b};\n\t"
        "}" : "=l"(r2) : "l"(u2));
    return r2;
}

__global__ void prep_kernel(const float* __restrict__ W1_0, const float* __restrict__ b1_0,
                            const float* __restrict__ W2_0, const float* __restrict__ b2_0,
                            const float* __restrict__ W1_1, const float* __restrict__ b1_1,
                            const float* __restrict__ W2_1, const float* __restrict__ b2_1)
{
    const int h = threadIdx.x;
    const float CEX = 2.8853900817779268f;  // 2*log2(e)
    const float vsgn = (h < NNEWT) ? 2.0f : -2.0f;
    #pragma unroll
    for (int ode = 0; ode < 2; ++ode) {
        const float* W1 = ode ? W1_1 : W1_0;
        const float* b1 = ode ? b1_1 : b1_0;
        const float* W2 = ode ? W2_1 : W2_0;
        float a0 = W1[h] * CEX, a1 = W1[HID + h] * CEX, a2 = W1[2 * HID + h] * CEX;
        float ab = b1[h] * CEX;
        float v0 = vsgn * W2[h * 3 + 0];
        float v1 = vsgn * W2[h * 3 + 1];
        float v2 = vsgn * W2[h * 3 + 2];
        g_scratch_w[ode][h][0] = make_ulonglong2(pk2(a0, a0), pk2(a1, a1));
        g_scratch_w[ode][h][1] = make_ulonglong2(pk2(a2, a2), pk2(ab, ab));
        g_scratch_w[ode][h][2] = make_ulonglong2(pk2(v0, v0), pk2(v1, v1));
        g_scratch_w[ode][h][3] = make_ulonglong2(pk2(v2, v2), 0ull);
        if (h < 3) {
            const float* b2 = ode ? b2_1 : b2_0;
            float s = b2[h];
            for (int k = 0; k < HID; ++k) s += W2[k * 3 + h];
            g_scratch_S[ode][h] = s;
        }
    }
}

__global__ void __launch_bounds__(TPB, 6)
diffeo_kernel(const float* __restrict__ coords,
              const float* __restrict__ img,
              float* __restrict__ out)
{
    const int tid = threadIdx.x;
    const int base = (blockIdx.x * TPB + tid) * PPT;

    // Load 6 points (18 floats, 8B-aligned) as 9x float2; pack 3 pairs
    u64 yx[NQ], yy[NQ], yz[NQ];
    {
        const float2* c2 = reinterpret_cast<const float2*>(coords + (size_t)base * 3);
        float2 a0 = c2[0], a1 = c2[1], a2c = c2[2];
        float2 a3 = c2[3], a4 = c2[4], a5 = c2[5];
        float2 a6 = c2[6], a7 = c2[7], a8 = c2[8];
        yx[0] = pk2(a0.x, a1.y);  yy[0] = pk2(a0.y, a2c.x);  yz[0] = pk2(a1.x, a2c.y);
        yx[1] = pk2(a3.x, a4.y);  yy[1] = pk2(a3.y, a5.x);   yz[1] = pk2(a4.x, a5.y);
        yx[2] = pk2(a6.x, a7.y);  yy[2] = pk2(a6.y, a8.x);   yz[2] = pk2(a7.x, a8.y);
    }

    const u64 ONE2   = 0x3F8000003F800000ull;
    const u64 TWO2   = 0x4000000040000000ull;
    const u64 NTWO2  = 0xC0000000C0000000ull;
    const u64 MAGIC2 = 0x7EF311C37EF311C3ull;
    const float hstep = 0.05f;

    #pragma unroll 1
    for (int ode = 0; ode < 2; ++ode) {
        const u64 S0d = pk2(c_S[ode][0], c_S[ode][0]);
        const u64 S1d = pk2(c_S[ode][1], c_S[ode][1]);
        const u64 S2d = pk2(c_S[ode][2], c_S[ode][2]);

        #pragma unroll 1
        for (int step = 0; step < 4; ++step) {
            u64 ax[NQ], ay[NQ], az[NQ], tx[NQ], ty[NQ], tz[NQ];
            #pragma unroll
            for (int q = 0; q < NQ; ++q) {
                ax[q] = yx[q]; ay[q] = yy[q]; az[q] = yz[q];
                tx[q] = yx[q]; ty[q] = yy[q]; tz[q] = yz[q];
            }

            #pragma unroll 1
            for (int s = 0; s < 4; ++s) {
                u64 kx[NQ], ky[NQ], kz[NQ];
                #pragma unroll
                for (int q = 0; q < NQ; ++q) { kx[q] = S0d; ky[q] = S1d; kz[q] = S2d; }

                // ---- Newton path: r = 1/(1+2^u); magic init via 64-bit subtract
                #pragma unroll 2
                for (int hh = 0; hh < NNEWT; ++hh) {
                    ulonglong2 g0 = c_w[ode][hh][0];
                    ulonglong2 g1 = c_w[ode][hh][1];
                    ulonglong2 g2 = c_w[ode][hh][2];
                    u64 v2d = c_w[ode][hh][3].x;
                    #pragma unroll
                    for (int q = 0; q < NQ; ++q) {
                        u64 u2 = fma2(tx[q], g0.x, fma2(ty[q], g0.y, fma2(tz[q], g1.x, g1.y)));
                        u64 e2 = ex2pair(u2);
                        u64 d2 = add2(e2, ONE2);
                        u64 r02 = MAGIC2 - d2;           // per-half magic rcp init (no borrow across 32)
                        u64 t1 = fma2(d2, r02, NTWO2);   // d*r0 - 2
                        u64 m1 = mul2(r02, t1);          // -r1
                        u64 t2 = fma2(d2, m1, TWO2);     // 2 - d*r1
                        u64 m2 = mul2(m1, t2);           // -r2   (r = -m2)
                        kx[q] = fma2(m2, g2.x, kx[q]);   // r*(-2W2) == m2*(+2W2)
                        ky[q] = fma2(m2, g2.y, ky[q]);
                        kz[q] = fma2(m2, v2d, kz[q]);
                    }
                }
                // ---- MUFU rcp path (C,D hold -2W2)
                #pragma unroll 2
                for (int hh = NNEWT; hh < HID; ++hh) {
                    ulonglong2 g0 = c_w[ode][hh][0];
                    ulonglong2 g1 = c_w[ode][hh][1];
                    ulonglong2 g2 = c_w[ode][hh][2];
                    u64 v2d = c_w[ode][hh][3].x;
                    #pragma unroll
                    for (int q = 0; q < NQ; ++q) {
                        u64 u2 = fma2(tx[q], g0.x, fma2(ty[q], g0.y, fma2(tz[q], g1.x, g1.y)));
                        u64 r2 = sigpair(u2);
                        kx[q] = fma2(r2, g2.x, kx[q]);
                        ky[q] = fma2(r2, g2.y, ky[q]);
                        kz[q] = fma2(r2, v2d, kz[q]);
                    }
                }

                float wa = (s == 0 || s == 3) ? (hstep * (1.0f / 6.0f)) : (hstep * (1.0f / 3.0f));
                float wn = (s < 2) ? (0.5f * hstep) : ((s == 2) ? hstep : 0.0f);
                u64 wa2 = pk2(wa, wa), wn2 = pk2(wn, wn);
                #pragma unroll
                for (int q = 0; q < NQ; ++q) {
                    ax[q] = fma2(wa2, kx[q], ax[q]);
                    ay[q] = fma2(wa2, ky[q], ay[q]);
                    az[q] = fma2(wa2, kz[q], az[q]);
                    tx[q] = fma2(wn2, kx[q], yx[q]);
                    ty[q] = fma2(wn2, ky[q], yy[q]);
                    tz[q] = fma2(wn2, kz[q], yz[q]);
                }
            }
            #pragma unroll
            for (int q = 0; q < NQ; ++q) { yx[q] = ax[q]; yy[q] = ay[q]; yz[q] = az[q]; }
        }
    }

    // Unpack final coords
    float fy[PPT][3];
    #pragma unroll
    for (int q = 0; q < NQ; ++q) {
        upk2(yx[q], fy[2*q][0], fy[2*q+1][0]);
        upk2(yy[q], fy[2*q][1], fy[2*q+1][1]);
        upk2(yz[q], fy[2*q][2], fy[2*q+1][2]);
    }

    // Trilinear grid sample of img (128^3), zeros padding, align_corners=False
    float regv[PPT];
    #pragma unroll
    for (int p = 0; p < PPT; ++p) {
        float xx = fmaf(fy[p][2], 64.0f, 63.5f);
        float yyc = fmaf(fy[p][1], 64.0f, 63.5f);
        float zz = fmaf(fy[p][0], 64.0f, 63.5f);
        float xf = floorf(xx), yf = floorf(yyc), zf = floorf(zz);
        float txw = xx - xf, tyw = yyc - yf, tzw = zz - zf;
        int x0 = (int)xf, y0i = (int)yf, z0 = (int)zf;

        float sacc = 0.0f;
        #pragma unroll
        for (int dz = 0; dz < 2; ++dz) {
            float wz = dz ? tzw : (1.0f - tzw);
            int zi = z0 + dz;
            #pragma unroll
            for (int dy = 0; dy < 2; ++dy) {
                float wy = dy ? tyw : (1.0f - tyw);
                int yi = y0i + dy;
                #pragma unroll
                for (int dx = 0; dx < 2; ++dx) {
                    float wx = dx ? txw : (1.0f - txw);
                    int xi = x0 + dx;
                    if ((unsigned)xi < 128u && (unsigned)yi < 128u && (unsigned)zi < 128u) {
                        float v = __ldg(&img[((size_t)zi * 128 + yi) * 128 + xi]);
                        sacc = fmaf(v, wz * wy * wx, sacc);
                    }
                }
            }
        }
        regv[p] = (sacc - 0.5f) * 2.0f;
    }
    {
        float2* o2 = reinterpret_cast<float2*>(out + base);
        o2[0] = make_float2(regv[0], regv[1]);
        o2[1] = make_float2(regv[2], regv[3]);
        o2[2] = make_float2(regv[4], regv[5]);
    }

    // Write c1 after reg_out: 18 floats as 9x float2 (8B-aligned)
    {
        float2* o2 = reinterpret_cast<float2*>(out + NPTS + (size_t)base * 3);
        o2[0] = make_float2(fy[0][0], fy[0][1]);
        o2[1] = make_float2(fy[0][2], fy[1][0]);
        o2[2] = make_float2(fy[1][1], fy[1][2]);
        o2[3] = make_float2(fy[2][0], fy[2][1]);
        o2[4] = make_float2(fy[2][2], fy[3][0]);
        o2[5] = make_float2(fy[3][1], fy[3][2]);
        o2[6] = make_float2(fy[4][0], fy[4][1]);
        o2[7] = make_float2(fy[4][2], fy[5][0]);
        o2[8] = make_float2(fy[5][1], fy[5][2]);
    }
}

extern "C" void kernel_launch(void* const* d_in, const int* in_sizes, int n_in,
                              void* d_out, int out_size)
{
    const float* coords = (const float*)d_in[0];
    const float* W1_0   = (const float*)d_in[1];
    const float* b1_0   = (const float*)d_in[2];
    const float* W2_0   = (const float*)d_in[3];
    const float* b2_0   = (const float*)d_in[4];
    const float* W1_1   = (const float*)d_in[5];
    const float* b1_1   = (const float*)d_in[6];
    const float* W2_1   = (const float*)d_in[7];
    const float* b2_1   = (const float*)d_in[8];
    const float* img    = (const float*)d_in[9];
    float* out = (float*)d_out;

    // 1) pack+prescale weights into device scratch
    prep_kernel<<<1, HID>>>(W1_0, b1_0, W2_0, b2_0, W1_1, b1_1, W2_1, b2_1);

    // 2) scratch -> constant bank (D2D memcpy, graph-capturable)
    void* sym_w = nullptr; void* sym_S = nullptr;
    cudaGetSymbolAddress(&sym_w, c_w);
    cudaGetSymbolAddress(&sym_S, c_S);
    void* src_w = nullptr; void* src_S = nullptr;
    cudaGetSymbolAddress(&src_w, g_scratch_w);
    cudaGetSymbolAddress(&src_S, g_scratch_S);
    cudaMemcpyAsync(sym_w, src_w, sizeof(ulonglong2) * 2 * HID * 4, cudaMemcpyDeviceToDevice, 0);
    cudaMemcpyAsync(sym_S, src_S, sizeof(float) * 2 * 4, cudaMemcpyDeviceToDevice, 0);

    // 3) main kernel
    const int nblocks = NPTS / (TPB * PPT);  // 1152
    diffeo_kernel<<<nblocks, TPB>>>(coords, img, out);
}

// round 16
// speedup vs baseline: 1.1161x; 1.1161x over previous
#include <cuda_runtime.h>

#define NPTS (96*96*96)   // 884736
#define HID 64
#define TPB 128
#define PPT 6             // points per thread = 3 packed pairs
#define NQ  3
#define NNEWT 48          // h in [0,NNEWT): FMA-Newton reciprocal; rest: MUFU rcp

typedef unsigned long long u64;

// Per-h weight record (4 x ulonglong2 = 64B):
//  A={w0d,w1d} B={w2d,bbd}  (W1 rows & b1, prescaled by 2*log2e, duplicated)
//  C={v0d,v1d} D={v2d,pad}  (h<NNEWT: +2*W2 dup; h>=NNEWT: -2*W2 dup)
__constant__ ulonglong2 c_w[2][HID][4];
__constant__ float      c_S[2][4];       // S_j = b2_j + sum_h W2[h][j]

__device__ ulonglong2 g_scratch_w[2][HID][4];
__device__ float      g_scratch_S[2][4];

__device__ __forceinline__ u64 pk2(float lo, float hi) {
    u64 r; asm("mov.b64 %0,{%1,%2};" : "=l"(r) : "f"(lo), "f"(hi)); return r;
}
__device__ __forceinline__ void upk2(u64 v, float& lo, float& hi) {
    asm("mov.b64 {%0,%1},%2;" : "=f"(lo), "=f"(hi) : "l"(v));
}
__device__ __forceinline__ u64 fma2(u64 a, u64 b, u64 c) {
    u64 d; asm("fma.rn.f32x2 %0,%1,%2,%3;" : "=l"(d) : "l"(a), "l"(b), "l"(c)); return d;
}
__device__ __forceinline__ u64 mul2(u64 a, u64 b) {
    u64 d; asm("mul.rn.f32x2 %0,%1,%2;" : "=l"(d) : "l"(a), "l"(b)); return d;
}
__device__ __forceinline__ u64 add2(u64 a, u64 b) {
    u64 d; asm("add.rn.f32x2 %0,%1,%2;" : "=l"(d) : "l"(a), "l"(b)); return d;
}
// e2 = 2^(u2) per packed lane
__device__ __forceinline__ u64 ex2pair(u64 u2) {
    u64 e2;
    asm("{\n\t"
        ".reg .f32 a, b;\n\t"
        "mov.b64 {a, b}, %1;\n\t"
        "ex2.approx.f32 a, a;\n\t"
        "ex2.approx.f32 b, b;\n\t"
        "mov.b64 %0, {a, b};\n\t"
        "}" : "=l"(e2) : "l"(u2));
    return e2;
}
// r2 = 1/(1+2^u) per packed lane
__device__ __forceinline__ u64 sigpair(u64 u2) {
    u64 r2;
    asm("{\n\t"
        ".reg .f32 a, b;\n\t"
        "mov.b64 {a, b}, %1;\n\t"
        "ex2.approx.f32 a, a;\n\t"
        "ex2.approx.f32 b, b;\n\t"
        "add.f32 a, a, 0f3F800000;\n\t"
        "add.f32 b, b, 0f3F800000;\n\t"
        "rcp.approx.f32 a, a;\n\t"
        "rcp.approx.f32 b, b;\n\t"
        "mov.b64 %0, {a, b};\n\t"
        "}" : "=l"(r2) : "l"(u2));
    return r2;
}

__global__ void prep_kernel(const float* __restrict__ W1_0, const float* __restrict__ b1_0,
                            const float* __restrict__ W2_0, const float* __restrict__ b2_0,
                            const float* __restrict__ W1_1, const float* __restrict__ b1_1,
                            const float* __restrict__ W2_1, const float* __restrict__ b2_1)
{
    const int h = threadIdx.x;
    const float CEX = 2.8853900817779268f;  // 2*log2(e)
    const float vsgn = (h < NNEWT) ? 2.0f : -2.0f;
    #pragma unroll
    for (int ode = 0; ode < 2; ++ode) {
        const float* W1 = ode ? W1_1 : W1_0;
        const float* b1 = ode ? b1_1 : b1_0;
        const float* W2 = ode ? W2_1 : W2_0;
        float a0 = W1[h] * CEX, a1 = W1[HID + h] * CEX, a2 = W1[2 * HID + h] * CEX;
        float ab = b1[h] * CEX;
        float v0 = vsgn * W2[h * 3 + 0];
        float v1 = vsgn * W2[h * 3 + 1];
        float v2 = vsgn * W2[h * 3 + 2];
        g_scratch_w[ode][h][0] = make_ulonglong2(pk2(a0, a0), pk2(a1, a1));
        g_scratch_w[ode][h][1] = make_ulonglong2(pk2(a2, a2), pk2(ab, ab));
        g_scratch_w[ode][h][2] = make_ulonglong2(pk2(v0, v0), pk2(v1, v1));
        g_scratch_w[ode][h][3] = make_ulonglong2(pk2(v2, v2), 0ull);
        if (h < 3) {
            const float* b2 = ode ? b2_1 : b2_0;
            float s = b2[h];
            for (int k = 0; k < HID; ++k) s += W2[k * 3 + h];
            g_scratch_S[ode][h] = s;
        }
    }
}

__global__ void __launch_bounds__(TPB)
diffeo_kernel(const float* __restrict__ coords,
              const float* __restrict__ img,
              float* __restrict__ out)
{
    const int tid = threadIdx.x;
    const int base = (blockIdx.x * TPB + tid) * PPT;

    // Load 6 points (18 floats, 8B-aligned) as 9x float2; pack 3 pairs
    u64 yx[NQ], yy[NQ], yz[NQ];
    {
        const float2* c2 = reinterpret_cast<const float2*>(coords + (size_t)base * 3);
        float2 a0 = c2[0], a1 = c2[1], a2c = c2[2];
        float2 a3 = c2[3], a4 = c2[4], a5 = c2[5];
        float2 a6 = c2[6], a7 = c2[7], a8 = c2[8];
        yx[0] = pk2(a0.x, a1.y);  yy[0] = pk2(a0.y, a2c.x);  yz[0] = pk2(a1.x, a2c.y);
        yx[1] = pk2(a3.x, a4.y);  yy[1] = pk2(a3.y, a5.x);   yz[1] = pk2(a4.x, a5.y);
        yx[2] = pk2(a6.x, a7.y);  yy[2] = pk2(a6.y, a8.x);   yz[2] = pk2(a7.x, a8.y);
    }

    const u64 ONE2   = 0x3F8000003F800000ull;
    const u64 TWO2   = 0x4000000040000000ull;
    const u64 NTWO2  = 0xC0000000C0000000ull;
    const u64 MAGIC2 = 0x7EF311C37EF311C3ull;
    const float hstep = 0.05f;

    #pragma unroll 1
    for (int ode = 0; ode < 2; ++ode) {
        const u64 S0d = pk2(c_S[ode][0], c_S[ode][0]);
        const u64 S1d = pk2(c_S[ode][1], c_S[ode][1]);
        const u64 S2d = pk2(c_S[ode][2], c_S[ode][2]);

        #pragma unroll 1
        for (int step = 0; step < 4; ++step) {
            u64 ax[NQ], ay[NQ], az[NQ], tx[NQ], ty[NQ], tz[NQ];
            #pragma unroll
            for (int q = 0; q < NQ; ++q) {
                ax[q] = yx[q]; ay[q] = yy[q]; az[q] = yz[q];
                tx[q] = yx[q]; ty[q] = yy[q]; tz[q] = yz[q];
            }

            #pragma unroll 1
            for (int s = 0; s < 4; ++s) {
                u64 kx[NQ], ky[NQ], kz[NQ];
                #pragma unroll
                for (int q = 0; q < NQ; ++q) { kx[q] = S0d; ky[q] = S1d; kz[q] = S2d; }

                // ---- Newton path: r = 1/(1+2^u); magic init via 64-bit subtract
                #pragma unroll 2
                for (int hh = 0; hh < NNEWT; ++hh) {
                    ulonglong2 g0 = c_w[ode][hh][0];
                    ulonglong2 g1 = c_w[ode][hh][1];
                    ulonglong2 g2 = c_w[ode][hh][2];
                    u64 v2d = c_w[ode][hh][3].x;
                    #pragma unroll
                    for (int q = 0; q < NQ; ++q) {
                        u64 u2 = fma2(tx[q], g0.x, fma2(ty[q], g0.y, fma2(tz[q], g1.x, g1.y)));
                        u64 e2 = ex2pair(u2);
                        u64 d2 = add2(e2, ONE2);
                        u64 r02 = MAGIC2 - d2;           // per-half magic rcp init (no borrow across 32)
                        u64 t1 = fma2(d2, r02, NTWO2);   // d*r0 - 2
                        u64 m1 = mul2(r02, t1);          // -r1
                        u64 t2 = fma2(d2, m1, TWO2);     // 2 - d*r1
                        u64 m2 = mul2(m1, t2);           // -r2   (r = -m2)
                        kx[q] = fma2(m2, g2.x, kx[q]);   // r*(-2W2) == m2*(+2W2)
                        ky[q] = fma2(m2, g2.y, ky[q]);
                        kz[q] = fma2(m2, v2d, kz[q]);
                    }
                }
                // ---- MUFU rcp path (C,D hold -2W2)
                #pragma unroll 2
                for (int hh = NNEWT; hh < HID; ++hh) {
                    ulonglong2 g0 = c_w[ode][hh][0];
                    ulonglong2 g1 = c_w[ode][hh][1];
                    ulonglong2 g2 = c_w[ode][hh][2];
                    u64 v2d = c_w[ode][hh][3].x;
                    #pragma unroll
                    for (int q = 0; q < NQ; ++q) {
                        u64 u2 = fma2(tx[q], g0.x, fma2(ty[q], g0.y, fma2(tz[q], g1.x, g1.y)));
                        u64 r2 = sigpair(u2);
                        kx[q] = fma2(r2, g2.x, kx[q]);
                        ky[q] = fma2(r2, g2.y, ky[q]);
                        kz[q] = fma2(r2, v2d, kz[q]);
                    }
                }

                float wa = (s == 0 || s == 3) ? (hstep * (1.0f / 6.0f)) : (hstep * (1.0f / 3.0f));
                float wn = (s < 2) ? (0.5f * hstep) : ((s == 2) ? hstep : 0.0f);
                u64 wa2 = pk2(wa, wa), wn2 = pk2(wn, wn);
                #pragma unroll
                for (int q = 0; q < NQ; ++q) {
                    ax[q] = fma2(wa2, kx[q], ax[q]);
                    ay[q] = fma2(wa2, ky[q], ay[q]);
                    az[q] = fma2(wa2, kz[q], az[q]);
                    tx[q] = fma2(wn2, kx[q], yx[q]);
                    ty[q] = fma2(wn2, ky[q], yy[q]);
                    tz[q] = fma2(wn2, kz[q], yz[q]);
                }
            }
            #pragma unroll
            for (int q = 0; q < NQ; ++q) { yx[q] = ax[q]; yy[q] = ay[q]; yz[q] = az[q]; }
        }
    }

    // Unpack final coords
    float fy[PPT][3];
    #pragma unroll
    for (int q = 0; q < NQ; ++q) {
        upk2(yx[q], fy[2*q][0], fy[2*q+1][0]);
        upk2(yy[q], fy[2*q][1], fy[2*q+1][1]);
        upk2(yz[q], fy[2*q][2], fy[2*q+1][2]);
    }

    // Trilinear grid sample of img (128^3), zeros padding, align_corners=False
    float regv[PPT];
    #pragma unroll
    for (int p = 0; p < PPT; ++p) {
        float xx = fmaf(fy[p][2], 64.0f, 63.5f);
        float yyc = fmaf(fy[p][1], 64.0f, 63.5f);
        float zz = fmaf(fy[p][0], 64.0f, 63.5f);
        float xf = floorf(xx), yf = floorf(yyc), zf = floorf(zz);
        float txw = xx - xf, tyw = yyc - yf, tzw = zz - zf;
        int x0 = (int)xf, y0i = (int)yf, z0 = (int)zf;

        float sacc = 0.0f;
        #pragma unroll
        for (int dz = 0; dz < 2; ++dz) {
            float wz = dz ? tzw : (1.0f - tzw);
            int zi = z0 + dz;
            #pragma unroll
            for (int dy = 0; dy < 2; ++dy) {
                float wy = dy ? tyw : (1.0f - tyw);
                int yi = y0i + dy;
                #pragma unroll
                for (int dx = 0; dx < 2; ++dx) {
                    float wx = dx ? txw : (1.0f - txw);
                    int xi = x0 + dx;
                    if ((unsigned)xi < 128u && (unsigned)yi < 128u && (unsigned)zi < 128u) {
                        float v = __ldg(&img[((size_t)zi * 128 + yi) * 128 + xi]);
                        sacc = fmaf(v, wz * wy * wx, sacc);
                    }
                }
            }
        }
        regv[p] = (sacc - 0.5f) * 2.0f;
    }
    {
        float2* o2 = reinterpret_cast<float2*>(out + base);
        o2[0] = make_float2(regv[0], regv[1]);
        o2[1] = make_float2(regv[2], regv[3]);
        o2[2] = make_float2(regv[4], regv[5]);
    }

    // Write c1 after reg_out: 18 floats as 9x float2 (8B-aligned)
    {
        float2* o2 = reinterpret_cast<float2*>(out + NPTS + (size_t)base * 3);
        o2[0] = make_float2(fy[0][0], fy[0][1]);
        o2[1] = make_float2(fy[0][2], fy[1][0]);
        o2[2] = make_float2(fy[1][1], fy[1][2]);
        o2[3] = make_float2(fy[2][0], fy[2][1]);
        o2[4] = make_float2(fy[2][2], fy[3][0]);
        o2[5] = make_float2(fy[3][1], fy[3][2]);
        o2[6] = make_float2(fy[4][0], fy[4][1]);
        o2[7] = make_float2(fy[4][2], fy[5][0]);
        o2[8] = make_float2(fy[5][1], fy[5][2]);
    }
}

extern "C" void kernel_launch(void* const* d_in, const int* in_sizes, int n_in,
                              void* d_out, int out_size)
{
    const float* coords = (const float*)d_in[0];
    const float* W1_0   = (const float*)d_in[1];
    const float* b1_0   = (const float*)d_in[2];
    const float* W2_0   = (const float*)d_in[3];
    const float* b2_0   = (const float*)d_in[4];
    const float* W1_1   = (const float*)d_in[5];
    const float* b1_1   = (const float*)d_in[6];
    const float* W2_1   = (const float*)d_in[7];
    const float* b2_1   = (const float*)d_in[8];
    const float* img    = (const float*)d_in[9];
    float* out = (float*)d_out;

    // 1) pack+prescale weights into device scratch
    prep_kernel<<<1, HID>>>(W1_0, b1_0, W2_0, b2_0, W1_1, b1_1, W2_1, b2_1);

    // 2) scratch -> constant bank (D2D memcpy, graph-capturable)
    void* sym_w = nullptr; void* sym_S = nullptr;
    cudaGetSymbolAddress(&sym_w, c_w);
    cudaGetSymbolAddress(&sym_S, c_S);
    void* src_w = nullptr; void* src_S = nullptr;
    cudaGetSymbolAddress(&src_w, g_scratch_w);
    cudaGetSymbolAddress(&src_S, g_scratch_S);
    cudaMemcpyAsync(sym_w, src_w, sizeof(ulonglong2) * 2 * HID * 4, cudaMemcpyDeviceToDevice, 0);
    cudaMemcpyAsync(sym_S, src_S, sizeof(float) * 2 * 4, cudaMemcpyDeviceToDevice, 0);

    // 3) main kernel
    const int nblocks = NPTS / (TPB * PPT);  // 1152
    diffeo_kernel<<<nblocks, TPB>>>(coords, img, out);
}

// round 17
// speedup vs baseline: 1.1317x; 1.0140x over previous
#include <cuda_runtime.h>

#define NPTS (96*96*96)   // 884736
#define HID 64
#define TPB 128
#define PPT 6             // points per thread = 3 packed pairs
#define NQ  3
// rcp role: h % 4 == 3  (16 of 64); others Newton (48 of 64) — same mix as champion

typedef unsigned long long u64;

// Per-h weight record (4 x ulonglong2 = 64B):
//  A={w0d,w1d} B={w2d,bbd}  (W1 rows & b1, prescaled by 2*log2e, duplicated)
//  C={v0d,v1d} D={v2d,pad}  (Newton h: +2*W2 dup; rcp h: -2*W2 dup)
__constant__ ulonglong2 c_w[2][HID][4];
__constant__ float      c_S[2][4];       // S_j = b2_j + sum_h W2[h][j]

__device__ ulonglong2 g_scratch_w[2][HID][4];
__device__ float      g_scratch_S[2][4];

__device__ __forceinline__ u64 pk2(float lo, float hi) {
    u64 r; asm("mov.b64 %0,{%1,%2};" : "=l"(r) : "f"(lo), "f"(hi)); return r;
}
__device__ __forceinline__ void upk2(u64 v, float& lo, float& hi) {
    asm("mov.b64 {%0,%1},%2;" : "=f"(lo), "=f"(hi) : "l"(v));
}
__device__ __forceinline__ u64 fma2(u64 a, u64 b, u64 c) {
    u64 d; asm("fma.rn.f32x2 %0,%1,%2,%3;" : "=l"(d) : "l"(a), "l"(b), "l"(c)); return d;
}
__device__ __forceinline__ u64 mul2(u64 a, u64 b) {
    u64 d; asm("mul.rn.f32x2 %0,%1,%2;" : "=l"(d) : "l"(a), "l"(b)); return d;
}
__device__ __forceinline__ u64 add2(u64 a, u64 b) {
    u64 d; asm("add.rn.f32x2 %0,%1,%2;" : "=l"(d) : "l"(a), "l"(b)); return d;
}
// e2 = 2^(u2) per packed lane
__device__ __forceinline__ u64 ex2pair(u64 u2) {
    u64 e2;
    asm("{\n\t"
        ".reg .f32 a, b;\n\t"
        "mov.b64 {a, b}, %1;\n\t"
        "ex2.approx.f32 a, a;\n\t"
        "ex2.approx.f32 b, b;\n\t"
        "mov.b64 %0, {a, b};\n\t"
        "}" : "=l"(e2) : "l"(u2));
    return e2;
}
// r2 = 1/(1+2^u) per packed lane
__device__ __forceinline__ u64 sigpair(u64 u2) {
    u64 r2;
    asm("{\n\t"
        ".reg .f32 a, b;\n\t"
        "mov.b64 {a, b}, %1;\n\t"
        "ex2.approx.f32 a, a;\n\t"
        "ex2.approx.f32 b, b;\n\t"
        "add.f32 a, a, 0f3F800000;\n\t"
        "add.f32 b, b, 0f3F800000;\n\t"
        "rcp.approx.f32 a, a;\n\t"
        "rcp.approx.f32 b, b;\n\t"
        "mov.b64 %0, {a, b};\n\t"
        "}" : "=l"(r2) : "l"(u2));
    return r2;
}

__global__ void prep_kernel(const float* __restrict__ W1_0, const float* __restrict__ b1_0,
                            const float* __restrict__ W2_0, const float* __restrict__ b2_0,
                            const float* __restrict__ W1_1, const float* __restrict__ b1_1,
                            const float* __restrict__ W2_1, const float* __restrict__ b2_1)
{
    const int h = threadIdx.x;
    const float CEX = 2.8853900817779268f;  // 2*log2(e)
    const float vsgn = ((h & 3) == 3) ? -2.0f : 2.0f;   // h%4==3 -> rcp path
    #pragma unroll
    for (int ode = 0; ode < 2; ++ode) {
        const float* W1 = ode ? W1_1 : W1_0;
        const float* b1 = ode ? b1_1 : b1_0;
        const float* W2 = ode ? W2_1 : W2_0;
        float a0 = W1[h] * CEX, a1 = W1[HID + h] * CEX, a2 = W1[2 * HID + h] * CEX;
        float ab = b1[h] * CEX;
        float v0 = vsgn * W2[h * 3 + 0];
        float v1 = vsgn * W2[h * 3 + 1];
        float v2 = vsgn * W2[h * 3 + 2];
        g_scratch_w[ode][h][0] = make_ulonglong2(pk2(a0, a0), pk2(a1, a1));
        g_scratch_w[ode][h][1] = make_ulonglong2(pk2(a2, a2), pk2(ab, ab));
        g_scratch_w[ode][h][2] = make_ulonglong2(pk2(v0, v0), pk2(v1, v1));
        g_scratch_w[ode][h][3] = make_ulonglong2(pk2(v2, v2), 0ull);
        if (h < 3) {
            const float* b2 = ode ? b2_1 : b2_0;
            float s = b2[h];
            for (int k = 0; k < HID; ++k) s += W2[k * 3 + h];
            g_scratch_S[ode][h] = s;
        }
    }
}

__global__ void __launch_bounds__(TPB)
diffeo_kernel(const float* __restrict__ coords,
              const float* __restrict__ img,
              float* __restrict__ out)
{
    const int tid = threadIdx.x;
    const int base = (blockIdx.x * TPB + tid) * PPT;

    // Load 6 points (18 floats, 8B-aligned) as 9x float2; pack 3 pairs
    u64 yx[NQ], yy[NQ], yz[NQ];
    {
        const float2* c2 = reinterpret_cast<const float2*>(coords + (size_t)base * 3);
        float2 a0 = c2[0], a1 = c2[1], a2c = c2[2];
        float2 a3 = c2[3], a4 = c2[4], a5 = c2[5];
        float2 a6 = c2[6], a7 = c2[7], a8 = c2[8];
        yx[0] = pk2(a0.x, a1.y);  yy[0] = pk2(a0.y, a2c.x);  yz[0] = pk2(a1.x, a2c.y);
        yx[1] = pk2(a3.x, a4.y);  yy[1] = pk2(a3.y, a5.x);   yz[1] = pk2(a4.x, a5.y);
        yx[2] = pk2(a6.x, a7.y);  yy[2] = pk2(a6.y, a8.x);   yz[2] = pk2(a7.x, a8.y);
    }

    const u64 ONE2   = 0x3F8000003F800000ull;
    const u64 TWO2   = 0x4000000040000000ull;
    const u64 NTWO2  = 0xC0000000C0000000ull;
    const u64 MAGIC2 = 0x7EF311C37EF311C3ull;
    const float hstep = 0.05f;

    #pragma unroll 1
    for (int ode = 0; ode < 2; ++ode) {
        const u64 S0d = pk2(c_S[ode][0], c_S[ode][0]);
        const u64 S1d = pk2(c_S[ode][1], c_S[ode][1]);
        const u64 S2d = pk2(c_S[ode][2], c_S[ode][2]);

        #pragma unroll 1
        for (int step = 0; step < 4; ++step) {
            u64 ax[NQ], ay[NQ], az[NQ], tx[NQ], ty[NQ], tz[NQ];
            #pragma unroll
            for (int q = 0; q < NQ; ++q) {
                ax[q] = yx[q]; ay[q] = yy[q]; az[q] = yz[q];
                tx[q] = yx[q]; ty[q] = yy[q]; tz[q] = yz[q];
            }

            #pragma unroll 1
            for (int s = 0; s < 4; ++s) {
                u64 kx[NQ], ky[NQ], kz[NQ];
                #pragma unroll
                for (int q = 0; q < NQ; ++q) { kx[q] = S0d; ky[q] = S1d; kz[q] = S2d; }

                // ---- Interleaved groups of 4: 3x Newton + 1x MUFU-rcp
                #pragma unroll 1
                for (int g = 0; g < HID / 4; ++g) {
                    const int hb = g * 4;
                    // 3 Newton h's (FMA-reciprocal, 2 MUFU each)
                    #pragma unroll
                    for (int j = 0; j < 3; ++j) {
                        const int hh = hb + j;
                        ulonglong2 g0 = c_w[ode][hh][0];
                        ulonglong2 g1 = c_w[ode][hh][1];
                        ulonglong2 g2 = c_w[ode][hh][2];
                        u64 v2d = c_w[ode][hh][3].x;
                        #pragma unroll
                        for (int q = 0; q < NQ; ++q) {
                            u64 u2 = fma2(tx[q], g0.x, fma2(ty[q], g0.y, fma2(tz[q], g1.x, g1.y)));
                            u64 e2 = ex2pair(u2);
                            u64 d2 = add2(e2, ONE2);
                            u64 r02 = MAGIC2 - d2;           // per-half magic rcp init
                            u64 t1 = fma2(d2, r02, NTWO2);   // d*r0 - 2
                            u64 m1 = mul2(r02, t1);          // -r1
                            u64 t2 = fma2(d2, m1, TWO2);     // 2 - d*r1
                            u64 m2 = mul2(m1, t2);           // -r2   (r = -m2)
                            kx[q] = fma2(m2, g2.x, kx[q]);   // r*(-2W2) == m2*(+2W2)
                            ky[q] = fma2(m2, g2.y, ky[q]);
                            kz[q] = fma2(m2, v2d, kz[q]);
                        }
                    }
                    // 1 rcp h (4 MUFU, FMA-light) — balances pipes locally
                    {
                        const int hh = hb + 3;
                        ulonglong2 g0 = c_w[ode][hh][0];
                        ulonglong2 g1 = c_w[ode][hh][1];
                        ulonglong2 g2 = c_w[ode][hh][2];
                        u64 v2d = c_w[ode][hh][3].x;
                        #pragma unroll
                        for (int q = 0; q < NQ; ++q) {
                            u64 u2 = fma2(tx[q], g0.x, fma2(ty[q], g0.y, fma2(tz[q], g1.x, g1.y)));
                            u64 r2 = sigpair(u2);
                            kx[q] = fma2(r2, g2.x, kx[q]);
                            ky[q] = fma2(r2, g2.y, ky[q]);
                            kz[q] = fma2(r2, v2d, kz[q]);
                        }
                    }
                }

                float wa = (s == 0 || s == 3) ? (hstep * (1.0f / 6.0f)) : (hstep * (1.0f / 3.0f));
                float wn = (s < 2) ? (0.5f * hstep) : ((s == 2) ? hstep : 0.0f);
                u64 wa2 = pk2(wa, wa), wn2 = pk2(wn, wn);
                #pragma unroll
                for (int q = 0; q < NQ; ++q) {
                    ax[q] = fma2(wa2, kx[q], ax[q]);
                    ay[q] = fma2(wa2, ky[q], ay[q]);
                    az[q] = fma2(wa2, kz[q], az[q]);
                    tx[q] = fma2(wn2, kx[q], yx[q]);
                    ty[q] = fma2(wn2, ky[q], yy[q]);
                    tz[q] = fma2(wn2, kz[q], yz[q]);
                }
            }
            #pragma unroll
            for (int q = 0; q < NQ; ++q) { yx[q] = ax[q]; yy[q] = ay[q]; yz[q] = az[q]; }
        }
    }

    // Unpack final coords
    float fy[PPT][3];
    #pragma unroll
    for (int q = 0; q < NQ; ++q) {
        upk2(yx[q], fy[2*q][0], fy[2*q+1][0]);
        upk2(yy[q], fy[2*q][1], fy[2*q+1][1]);
        upk2(yz[q], fy[2*q][2], fy[2*q+1][2]);
    }

    // Trilinear grid sample of img (128^3), zeros padding, align_corners=False
    float regv[PPT];
    #pragma unroll
    for (int p = 0; p < PPT; ++p) {
        float xx = fmaf(fy[p][2], 64.0f, 63.5f);
        float yyc = fmaf(fy[p][1], 64.0f, 63.5f);
        float zz = fmaf(fy[p][0], 64.0f, 63.5f);
        float xf = floorf(xx), yf = floorf(yyc), zf = floorf(zz);
        float txw = xx - xf, tyw = yyc - yf, tzw = zz - zf;
        int x0 = (int)xf, y0i = (int)yf, z0 = (int)zf;

        float sacc = 0.0f;
        #pragma unroll
        for (int dz = 0; dz < 2; ++dz) {
            float wz = dz ? tzw : (1.0f - tzw);
            int zi = z0 + dz;
            #pragma unroll
            for (int dy = 0; dy < 2; ++dy) {
                float wy = dy ? tyw : (1.0f - tyw);
                int yi = y0i + dy;
                #pragma unroll
                for (int dx = 0; dx < 2; ++dx) {
                    float wx = dx ? txw : (1.0f - txw);
                    int xi = x0 + dx;
                    if ((unsigned)xi < 128u && (unsigned)yi < 128u && (unsigned)zi < 128u) {
                        float v = __ldg(&img[((size_t)zi * 128 + yi) * 128 + xi]);
                        sacc = fmaf(v, wz * wy * wx, sacc);
                    }
                }
            }
        }
        regv[p] = (sacc - 0.5f) * 2.0f;
    }
    {
        float2* o2 = reinterpret_cast<float2*>(out + base);
        o2[0] = make_float2(regv[0], regv[1]);
        o2[1] = make_float2(regv[2], regv[3]);
        o2[2] = make_float2(regv[4], regv[5]);
    }

    // Write c1 after reg_out: 18 floats as 9x float2 (8B-aligned)
    {
        float2* o2 = reinterpret_cast<float2*>(out + NPTS + (size_t)base * 3);
        o2[0] = make_float2(fy[0][0], fy[0][1]);
        o2[1] = make_float2(fy[0][2], fy[1][0]);
        o2[2] = make_float2(fy[1][1], fy[1][2]);
        o2[3] = make_float2(fy[2][0], fy[2][1]);
        o2[4] = make_float2(fy[2][2], fy[3][0]);
        o2[5] = make_float2(fy[3][1], fy[3][2]);
        o2[6] = make_float2(fy[4][0], fy[4][1]);
        o2[7] = make_float2(fy[4][2], fy[5][0]);
        o2[8] = make_float2(fy[5][1], fy[5][2]);
    }
}

extern "C" void kernel_launch(void* const* d_in, const int* in_sizes, int n_in,
                              void* d_out, int out_size)
{
    const float* coords = (const float*)d_in[0];
    const float* W1_0   = (const float*)d_in[1];
    const float* b1_0   = (const float*)d_in[2];
    const float* W2_0   = (const float*)d_in[3];
    const float* b2_0   = (const float*)d_in[4];
    const float* W1_1   = (const float*)d_in[5];
    const float* b1_1   = (const float*)d_in[6];
    const float* W2_1   = (const float*)d_in[7];
    const float* b2_1   = (const float*)d_in[8];
    const float* img    = (const float*)d_in[9];
    float* out = (float*)d_out;

    // 1) pack+prescale weights into device scratch
    prep_kernel<<<1, HID>>>(W1_0, b1_0, W2_0, b2_0, W1_1, b1_1, W2_1, b2_1);

    // 2) scratch -> constant bank (D2D memcpy, graph-capturable)
    void* sym_w = nullptr; void* sym_S = nullptr;
    cudaGetSymbolAddress(&sym_w, c_w);
    cudaGetSymbolAddress(&sym_S, c_S);
    void* src_w = nullptr; void* src_S = nullptr;
    cudaGetSymbolAddress(&src_w, g_scratch_w);
    cudaGetSymbolAddress(&src_S, g_scratch_S);
    cudaMemcpyAsync(sym_w, src_w, sizeof(ulonglong2) * 2 * HID * 4, cudaMemcpyDeviceToDevice, 0);
    cudaMemcpyAsync(sym_S, src_S, sizeof(float) * 2 * 4, cudaMemcpyDeviceToDevice, 0);

    // 3) main kernel
    const int nblocks = NPTS / (TPB * PPT);  // 1152
    diffeo_kernel<<<nblocks, TPB>>>(coords, img, out);
}